// round 12
// baseline (speedup 1.0000x reference)
#include <cuda_runtime.h>
#include <stdint.h>

// ---------------- problem constants ----------------
#define MAXM      300000
#define NCLS      80
#define TOPK      1000
#define CONF      0.001f
#define NMSTH     0.5f
#define CLSOFF    4096.0f
#define CAND_CAP  4096
#define NB16      65536    // 16-bit histogram bins
#define NLCAP     384      // contested rows staged in static smem

// ---------------- device scratch (zero-initialized at load) ----------------
__device__ uint32_t g_scorebits[MAXM];
__device__ uint32_t g_hist16[NB16];    // reset by k_sup for next replay
__device__ uint32_t g_cand_cnt;        // reset by k_nms
__device__ unsigned long long g_cand[CAND_CAP];
// ranked top-k data (fully overwritten each replay)
__device__ float   g_x1[TOPK], g_y1[TOPK], g_x2[TOPK], g_y2[TOPK];
__device__ float   g_area[TOPK], g_scr[TOPK];
__device__ float4  g_box[TOPK];
__device__ int     g_lab[TOPK];
__device__ uint32_t g_sup[TOPK * 32];  // fully overwritten each replay
__device__ uint32_t g_rowNZ[32];       // reset by k_nms
__device__ uint32_t g_keep0[32];       // reset by k_nms

__device__ __forceinline__ float sigf(float x) {
    return 1.0f / (1.0f + expf(-x));
}

// ============================================================================
// K1: coalesced max-logit (4 lanes/anchor, 5 even float4 loads/lane)
//     512 threads, 512 anchors per block; fused score + 16-bit GLOBAL hist
// ============================================================================
__global__ void __launch_bounds__(512) k_score(const float* __restrict__ obj,
                                               const float* __restrict__ cls,
                                               int M) {
    int warp = threadIdx.x >> 5, lane = threadIdx.x & 31;
    int g = lane >> 2, s = lane & 3;            // 8 anchors/warp/iter, 4 lanes each
    int base = blockIdx.x * 512 + warp * 32;    // 16 warps x 32 anchors
    const float4* c4 = (const float4*)cls;

#pragma unroll
    for (int it = 0; it < 4; it++) {
        int m = base + it * 8 + g;
        float v = -1e30f;
        if (m < M) {
            const float4* row = c4 + (size_t)m * 20;
            float4 a0 = row[s];                 // 5 independent coalesced LDG.128
            float4 a1 = row[s + 4];
            float4 a2 = row[s + 8];
            float4 a3 = row[s + 12];
            float4 a4 = row[s + 16];
            float v0 = fmaxf(fmaxf(a0.x, a0.y), fmaxf(a0.z, a0.w));
            float v1 = fmaxf(fmaxf(a1.x, a1.y), fmaxf(a1.z, a1.w));
            float v2 = fmaxf(fmaxf(a2.x, a2.y), fmaxf(a2.z, a2.w));
            float v3 = fmaxf(fmaxf(a3.x, a3.y), fmaxf(a3.z, a3.w));
            float v4 = fmaxf(fmaxf(a4.x, a4.y), fmaxf(a4.z, a4.w));
            v = fmaxf(fmaxf(v0, v1), fmaxf(fmaxf(v2, v3), v4));
        }
        v = fmaxf(v, __shfl_down_sync(0xFFFFFFFFu, v, 2, 4));
        v = fmaxf(v, __shfl_down_sync(0xFFFFFFFFu, v, 1, 4));
        if (s == 0 && m < M) {
            // monotone: max_c sqrt(sig(o)*sig(c)) == sqrt(sig(o)*sig(max_c))
            float f = sqrtf(sigf(obj[m]) * sigf(v));
            uint32_t bits = __float_as_uint(f);
            g_scorebits[m] = bits;
            atomicAdd(&g_hist16[bits >> 16], 1u);   // spread-address REDG
        }
    }
}

// ============================================================================
// K2: INLINE redundant 16-bit select (every block) + gather
// ============================================================================
__global__ void __launch_bounds__(1024) k_gather(int M) {
    __shared__ uint32_t ssum[1024];
    __shared__ uint32_t sT;
    int t = threadIdx.x;

    // ---- per-block 64K-bin select: thread owns 64 bins (16 uint4) ----
    const uint4* h4 = (const uint4*)g_hist16;   // 16384 uint4
    uint32_t csum = 0;
#pragma unroll 4
    for (int i = 0; i < 16; i++) {
        uint4 v = __ldcg(&h4[t * 16 + i]);
        csum += v.x + v.y + v.z + v.w;
    }
    ssum[t] = csum;
    __syncthreads();
    for (int off = 1; off < 1024; off <<= 1) {
        uint32_t v = (t + off < 1024) ? ssum[t + off] : 0u;
        __syncthreads();
        ssum[t] += v;
        __syncthreads();
    }
    uint32_t cum = (t < 1023) ? ssum[t + 1] : 0u;   // strictly-above count
    if (cum < (uint32_t)TOPK && cum + csum >= (uint32_t)TOPK) {
        // crossing is in my 64-bin chunk: walk descending
        for (int i = 15; i >= 0; i--) {
            uint4 v = __ldcg(&h4[t * 16 + i]);
            uint32_t comp[4] = {v.w, v.z, v.y, v.x};
            const int boff[4] = {3, 2, 1, 0};
#pragma unroll
            for (int c = 0; c < 4; c++) {
                uint32_t bc = comp[c];
                if (bc > 0 && cum < (uint32_t)TOPK && cum + bc >= (uint32_t)TOPK)
                    sT = (uint32_t)(t * 64 + i * 4 + boff[c]) << 16;
                cum += bc;
            }
        }
    }
    __syncthreads();
    uint32_t T = sT;   // bin-start threshold: superset of exact top-1000

    // ---- gather (bits, idx) with bits >= T ----
    const uint4* sb4 = (const uint4*)g_scorebits;
    int n4 = M >> 2;
    for (int i = blockIdx.x * 1024 + t; i < n4; i += gridDim.x * 1024) {
        uint4 v = sb4[i];
        uint32_t m0 = (uint32_t)(i << 2);
        uint32_t bb[4] = {v.x, v.y, v.z, v.w};
#pragma unroll
        for (int c = 0; c < 4; c++) {
            if (bb[c] >= T) {
                uint32_t p = atomicAdd(&g_cand_cnt, 1u);
                if (p < CAND_CAP)
                    g_cand[p] = ((unsigned long long)bb[c] << 32) |
                                (unsigned long long)(0xFFFFFFFFu - (m0 + c));
            }
        }
    }
    if (blockIdx.x == 0 && t < (M & 3)) {
        uint32_t m = (uint32_t)((n4 << 2) + t);
        uint32_t b = g_scorebits[m];
        if (b >= T) {
            uint32_t p = atomicAdd(&g_cand_cnt, 1u);
            if (p < CAND_CAP)
                g_cand[p] = ((unsigned long long)b << 32) |
                            (unsigned long long)(0xFFFFFFFFu - m);
        }
    }
}

// ============================================================================
// K3: warp-per-candidate rank (ballot count) + warp-parallel argmax + fetch
// ============================================================================
__global__ void __launch_bounds__(1024) k_rank(const float* __restrict__ cls,
                                               const float4* __restrict__ boxp) {
    __shared__ unsigned long long keys[CAND_CAP];
    int t = threadIdx.x;
    uint32_t n = g_cand_cnt;
    if (n > CAND_CAP) n = CAND_CAP;
    if ((uint32_t)(blockIdx.x * 32) >= n) return;   // block-uniform early exit

    for (uint32_t i = t; i < n; i += 1024) keys[i] = g_cand[i];
    __syncthreads();

    int warp = t >> 5, lane = t & 31;
    uint32_t c = blockIdx.x * 32 + warp;
    if (c >= n) return;                              // warp-uniform
    unsigned long long k = keys[c];

    // warp-cooperative rank: lanes split the scan; count via ballot+popc
    int r = 0;
    for (uint32_t j0 = 0; j0 < n; j0 += 32) {
        uint32_t j = j0 + lane;
        bool p = (j < n) && (keys[j] > k);
        r += __popc(__ballot_sync(0xFFFFFFFFu, p));
    }
    if (r >= TOPK) return;

    uint32_t idx = 0xFFFFFFFFu - (uint32_t)(k & 0xFFFFFFFFull);

    // warp-parallel first-max argmax over 80 classes (20 lanes x 1 float4)
    float best = -1e30f;
    int lab = 0x7FFFFFFF;
    if (lane < 20) {
        float4 v = __ldg(&((const float4*)(cls + (size_t)idx * NCLS))[lane]);
        best = v.x; lab = lane * 4;
        if (v.y > best) { best = v.y; lab = lane * 4 + 1; }
        if (v.z > best) { best = v.z; lab = lane * 4 + 2; }
        if (v.w > best) { best = v.w; lab = lane * 4 + 3; }
    }
#pragma unroll
    for (int off = 16; off > 0; off >>= 1) {
        float ob = __shfl_down_sync(0xFFFFFFFFu, best, off);
        int   ol = __shfl_down_sync(0xFFFFFFFFu, lab, off);
        if (ob > best || (ob == best && ol < lab)) { best = ob; lab = ol; }
    }
    lab = __shfl_sync(0xFFFFFFFFu, lab, 0);          // first-max index

    if (lane == 0) {
        float scr = __uint_as_float((uint32_t)(k >> 32));
        float4 b = __ldg(&boxp[idx]);
        float off = (float)lab * CLSOFF;
        float x1 = b.x + off, y1 = b.y + off;
        float x2 = b.z + off, y2 = b.w + off;
        g_box[r] = b;
        g_scr[r] = scr;
        g_lab[r] = lab;
        g_x1[r] = x1; g_y1[r] = y1; g_x2[r] = x2; g_y2[r] = y2;
        g_area[r] = fmaxf(x2 - x1, 0.0f) * fmaxf(y2 - y1, 0.0f);
        if (scr > CONF) atomicOr(&g_keep0[r >> 5], 1u << (r & 31));
    }
}

// ============================================================================
// K4: suppression bit-matrix (32 blocks x 1024) + hist16 reset slice
// ============================================================================
__global__ void k_sup() {
    __shared__ float sx1[TOPK], sy1[TOPK], sx2[TOPK], sy2[TOPK], sarea[TOPK];
    __shared__ int   slab[TOPK];
    int t = threadIdx.x;
    for (int i = t; i < TOPK; i += 1024) {
        sx1[i] = g_x1[i]; sy1[i] = g_y1[i];
        sx2[i] = g_x2[i]; sy2[i] = g_y2[i];
        sarea[i] = g_area[i]; slab[i] = g_lab[i];
    }
    // reset this block's slice of hist16 for the next replay (512 uint4/block)
    if (t < 512) {
        uint4 z = {0, 0, 0, 0};
        ((uint4*)g_hist16)[blockIdx.x * 512 + t] = z;
    }
    __syncthreads();

    int w = t >> 5;          // j-word
    int lane = t & 31;       // row within this block's 32-row band
    int i = blockIdx.x * 32 + lane;
    int jbase = w * 32;
    uint32_t bits = 0;
    if (i < TOPK && jbase < i) {
        int lb = slab[i];
        float ix1 = sx1[i], iy1 = sy1[i], ix2 = sx2[i], iy2 = sy2[i];
        float ia = sarea[i];
        int jend = jbase + 32; if (jend > i) jend = i;
        for (int j = jbase; j < jend; j++) {
            if (slab[j] == lb) {   // cross-class IoU is exactly 0 (offset geometry)
                float xx1 = fmaxf(ix1, sx1[j]);
                float yy1 = fmaxf(iy1, sy1[j]);
                float xx2 = fminf(ix2, sx2[j]);
                float yy2 = fminf(iy2, sy2[j]);
                float inter = fmaxf(xx2 - xx1, 0.0f) * fmaxf(yy2 - yy1, 0.0f);
                float iou = inter / (ia + sarea[j] - inter + 1e-9f);
                if (iou > NMSTH) bits |= (1u << (j - jbase));
            }
        }
    }
    if (i < TOPK) {
        g_sup[i * 32 + w] = bits;
        if (bits) atomicOr(&g_rowNZ[i >> 5], 1u << (i & 31));
    }
}

// ============================================================================
// K5: sparse greedy sweep + output + remaining state reset
// ============================================================================
__global__ void k_nms(float* __restrict__ out, int out_size) {
    __shared__ uint32_t srow[NLCAP * 32];   // 48 KB: staged contested rows
    __shared__ int      list[1024];
    __shared__ int      nlist;
    __shared__ uint32_t keep[32];
    __shared__ uint32_t rnz[32];

    int t = threadIdx.x;
    int lane = t & 31;
    if (t < 32) { keep[t] = g_keep0[t]; rnz[t] = g_rowNZ[t]; }
    __syncthreads();

    // warp 0: build ascending list of contested rows
    if (t < 32) {
        int cnt = 0;
        for (int w2 = 0; w2 < 32; w2++) {
            uint32_t rb = rnz[w2];
            int bit = (rb >> lane) & 1;
            uint32_t bal = __ballot_sync(0xFFFFFFFFu, bit);
            if (bit) {
                int pos = cnt + __popc(bal & ((1u << lane) - 1u));
                list[pos] = w2 * 32 + lane;
            }
            cnt += __popc(bal);
        }
        if (lane == 0) nlist = cnt;
    }
    __syncthreads();

    // stage contested rows (first NLCAP) into smem
    int nl = nlist;
    for (int l = t >> 5; l < nl && l < NLCAP; l += 32)
        srow[l * 32 + lane] = g_sup[list[l] * 32 + lane];
    __syncthreads();

    // warp 0: serial greedy sweep, lane owns keep-word lane
    if (t < 32) {
        uint32_t kw = keep[lane];
        for (int l = 0; l < nl; l++) {
            int i = list[l];
            int iw = i >> 5;
            uint32_t ib = (uint32_t)(i & 31);
            uint32_t ltm = (lane < iw) ? 0xFFFFFFFFu
                         : ((lane == iw) ? ((1u << ib) - 1u) : 0u);
            uint32_t row = (l < NLCAP) ? srow[l * 32 + lane]
                                       : g_sup[i * 32 + lane];
            uint32_t v = row & kw & ltm;
            if (__any_sync(0xFFFFFFFFu, v != 0u)) {
                if (lane == iw) kw &= ~(1u << ib);
            }
        }
        keep[lane] = kw;
    }
    __syncthreads();

    if (t < TOPK) {
        float kf = ((keep[t >> 5] >> (t & 31)) & 1u) ? 1.0f : 0.0f;
        float4 b = g_box[t];   // raw (un-offset) box, matches reference
        out[t * 5 + 0] = g_scr[t] * kf;
        out[t * 5 + 1] = b.x * kf;
        out[t * 5 + 2] = b.y * kf;
        out[t * 5 + 3] = b.z * kf;
        out[t * 5 + 4] = b.w * kf;
        if (out_size >= 6000) out[5000 + t] = (float)g_lab[t];
        if (out_size >= 7000) out[6000 + t] = kf;
    }

    // ---- reset remaining scratch for the next replay ----
    if (t < 32) { g_rowNZ[t] = 0; g_keep0[t] = 0; }
    if (t == 0) g_cand_cnt = 0;
}

// ---------------- launch (5 kernels) ----------------
extern "C" void kernel_launch(void* const* d_in, const int* in_sizes, int n_in,
                              void* d_out, int out_size) {
    const float* obj   = (const float*)d_in[0];
    const float* cls   = (const float*)d_in[1];
    const float4* boxp = (const float4*)d_in[2];
    float* out = (float*)d_out;
    int M = in_sizes[0];
    if (M > MAXM) M = MAXM;
    (void)n_in;

    int gsc = (M + 511) / 512;
    int n4 = M >> 2;
    int gb = (n4 + 1023) / 1024;
    if (gb > 148) gb = 148;
    if (gb < 1) gb = 1;

    k_score<<<gsc, 512>>>(obj, cls, M);
    k_gather<<<gb, 1024>>>(M);
    k_rank<<<CAND_CAP / 32, 1024>>>(cls, boxp);
    k_sup<<<(TOPK + 31) / 32, 1024>>>();
    k_nms<<<1, 1024>>>(out, out_size);
}

// round 13
// speedup vs baseline: 2.8098x; 2.8098x over previous
#include <cuda_runtime.h>
#include <stdint.h>

// ---------------- problem constants ----------------
#define MAXM      300000
#define NCLS      80
#define TOPK      1000
#define CONF      0.001f
#define NMSTH     0.5f
#define CLSOFF    4096.0f
#define CAND_CAP  4096
#define NBINS     4096
#define NLCAP     384      // contested rows staged in static smem

// ---------------- device scratch (zero-initialized at load) ----------------
// All reset to zero at the END of k_nms for the next replay.
__device__ uint32_t g_scorebits[MAXM];
__device__ uint32_t g_hist1[NBINS];
__device__ uint32_t g_hist2[NBINS];
__device__ uint32_t g_prefix1;        // benign identical-value race (hist2 blocks)
__device__ uint32_t g_need;           // benign identical-value race (hist2 blocks)
__device__ uint32_t g_cand_cnt;
__device__ unsigned long long g_cand[CAND_CAP];
// ranked top-k data (fully overwritten each replay)
__device__ float   g_x1[TOPK], g_y1[TOPK], g_x2[TOPK], g_y2[TOPK];
__device__ float   g_area[TOPK], g_scr[TOPK];
__device__ float4  g_box[TOPK];
__device__ int     g_lab[TOPK];
__device__ uint32_t g_sup[TOPK * 32];  // fully overwritten each replay
__device__ uint32_t g_rowNZ[32];
__device__ uint32_t g_keep0[32];

__device__ __forceinline__ float sigf(float x) {
    return 1.0f / (1.0f + expf(-x));
}

// ============================================================================
// K1: coalesced max-logit (4 lanes/anchor, 5 even float4 loads/lane)
//     512 threads, 512 anchors per block; fused score + 12-bit hist
// ============================================================================
__global__ void __launch_bounds__(512) k_score(const float* __restrict__ obj,
                                               const float* __restrict__ cls,
                                               int M) {
    __shared__ uint32_t sh[NBINS];
    for (int i = threadIdx.x; i < NBINS; i += 512) sh[i] = 0;
    __syncthreads();

    int warp = threadIdx.x >> 5, lane = threadIdx.x & 31;
    int g = lane >> 2, s = lane & 3;            // 8 anchors/warp/iter, 4 lanes each
    int base = blockIdx.x * 512 + warp * 32;    // 16 warps x 32 anchors
    const float4* c4 = (const float4*)cls;

#pragma unroll
    for (int it = 0; it < 4; it++) {
        int m = base + it * 8 + g;
        float v = -1e30f;
        if (m < M) {
            const float4* row = c4 + (size_t)m * 20;
            float4 a0 = row[s];                 // 5 independent coalesced LDG.128
            float4 a1 = row[s + 4];
            float4 a2 = row[s + 8];
            float4 a3 = row[s + 12];
            float4 a4 = row[s + 16];
            float v0 = fmaxf(fmaxf(a0.x, a0.y), fmaxf(a0.z, a0.w));
            float v1 = fmaxf(fmaxf(a1.x, a1.y), fmaxf(a1.z, a1.w));
            float v2 = fmaxf(fmaxf(a2.x, a2.y), fmaxf(a2.z, a2.w));
            float v3 = fmaxf(fmaxf(a3.x, a3.y), fmaxf(a3.z, a3.w));
            float v4 = fmaxf(fmaxf(a4.x, a4.y), fmaxf(a4.z, a4.w));
            v = fmaxf(fmaxf(v0, v1), fmaxf(fmaxf(v2, v3), v4));
        }
        v = fmaxf(v, __shfl_down_sync(0xFFFFFFFFu, v, 2, 4));
        v = fmaxf(v, __shfl_down_sync(0xFFFFFFFFu, v, 1, 4));
        if (s == 0 && m < M) {
            // monotone: max_c sqrt(sig(o)*sig(c)) == sqrt(sig(o)*sig(max_c))
            float f = sqrtf(sigf(obj[m]) * sigf(v));
            uint32_t bits = __float_as_uint(f);
            g_scorebits[m] = bits;
            atomicAdd(&sh[bits >> 20], 1u);
        }
    }
    __syncthreads();
    for (int i = threadIdx.x; i < NBINS; i += 512) {
        uint32_t v = sh[i];
        if (v) atomicAdd(&g_hist1[i], v);
    }
}

// ============================================================================
// K2: INLINE redundant round-1 select (every block) + refinement hist
// ============================================================================
__global__ void __launch_bounds__(1024) k_hist2(int M) {
    __shared__ uint32_t sh[NBINS];
    __shared__ uint32_t ssum[1024];
    __shared__ uint32_t spre;
    int t = threadIdx.x;

    // ---- redundant round-1 select over g_hist1 (deterministic, per-block) ----
    uint4 a = __ldcg(&((const uint4*)g_hist1)[t]);
    uint32_t hh[4] = {a.x, a.y, a.z, a.w};
    ssum[t] = hh[0] + hh[1] + hh[2] + hh[3];
    __syncthreads();
    for (int off = 1; off < 1024; off <<= 1) {
        uint32_t v = (t + off < 1024) ? ssum[t + off] : 0u;
        __syncthreads();
        ssum[t] += v;
        __syncthreads();
    }
    uint32_t cum = (t < 1023) ? ssum[t + 1] : 0u;  // strictly-above count
#pragma unroll
    for (int c = 3; c >= 0; c--) {
        uint32_t bc = hh[c];
        if (bc > 0 && cum < (uint32_t)TOPK && cum + bc >= (uint32_t)TOPK) {
            uint32_t pre = (uint32_t)(t * 4 + c) << 20;
            spre = pre;
            g_prefix1 = pre;              // identical across blocks: benign race
            g_need = (uint32_t)TOPK - cum;
        }
        cum += bc;
    }
    sh[t] = 0; sh[t + 1024] = 0; sh[t + 2048] = 0; sh[t + 3072] = 0;
    __syncthreads();
    uint32_t pre = spre;

    // ---- refinement histogram over next 12 bits ----
    const uint4* sb4 = (const uint4*)g_scorebits;
    int n4 = M >> 2;
    for (int i = blockIdx.x * 1024 + t; i < n4; i += gridDim.x * 1024) {
        uint4 v = sb4[i];
        if ((v.x & 0xFFF00000u) == pre) atomicAdd(&sh[(v.x >> 8) & 0xFFFu], 1u);
        if ((v.y & 0xFFF00000u) == pre) atomicAdd(&sh[(v.y >> 8) & 0xFFFu], 1u);
        if ((v.z & 0xFFF00000u) == pre) atomicAdd(&sh[(v.z >> 8) & 0xFFFu], 1u);
        if ((v.w & 0xFFF00000u) == pre) atomicAdd(&sh[(v.w >> 8) & 0xFFFu], 1u);
    }
    if (blockIdx.x == 0 && t < (M & 3)) {
        uint32_t b = g_scorebits[(n4 << 2) + t];
        if ((b & 0xFFF00000u) == pre) atomicAdd(&sh[(b >> 8) & 0xFFFu], 1u);
    }
    __syncthreads();
    for (int i = t; i < NBINS; i += 1024) {
        uint32_t v = sh[i];
        if (v) atomicAdd(&g_hist2[i], v);
    }
}

// ============================================================================
// K3: INLINE redundant round-2 select (every block) + gather
// ============================================================================
__global__ void __launch_bounds__(1024) k_gather(int M) {
    __shared__ uint32_t ssum[1024];
    __shared__ uint32_t sT;
    int t = threadIdx.x;

    // ---- redundant round-2 select over g_hist2 ----
    uint32_t need = g_need;
    uint32_t pre1 = g_prefix1;
    uint4 a = __ldcg(&((const uint4*)g_hist2)[t]);
    uint32_t hh[4] = {a.x, a.y, a.z, a.w};
    ssum[t] = hh[0] + hh[1] + hh[2] + hh[3];
    __syncthreads();
    for (int off = 1; off < 1024; off <<= 1) {
        uint32_t v = (t + off < 1024) ? ssum[t + off] : 0u;
        __syncthreads();
        ssum[t] += v;
        __syncthreads();
    }
    uint32_t cum = (t < 1023) ? ssum[t + 1] : 0u;
#pragma unroll
    for (int c = 3; c >= 0; c--) {
        uint32_t bc = hh[c];
        if (bc > 0 && cum < need && cum + bc >= need)
            sT = pre1 | ((uint32_t)(t * 4 + c) << 8);   // final 24-bit threshold
        cum += bc;
    }
    __syncthreads();
    uint32_t T = sT;

    // ---- gather (bits, idx) with bits >= T ----
    const uint4* sb4 = (const uint4*)g_scorebits;
    int n4 = M >> 2;
    for (int i = blockIdx.x * 1024 + t; i < n4; i += gridDim.x * 1024) {
        uint4 v = sb4[i];
        uint32_t m0 = (uint32_t)(i << 2);
        uint32_t bb[4] = {v.x, v.y, v.z, v.w};
#pragma unroll
        for (int c = 0; c < 4; c++) {
            if (bb[c] >= T) {
                uint32_t p = atomicAdd(&g_cand_cnt, 1u);
                if (p < CAND_CAP)
                    g_cand[p] = ((unsigned long long)bb[c] << 32) |
                                (unsigned long long)(0xFFFFFFFFu - (m0 + c));
            }
        }
    }
    if (blockIdx.x == 0 && t < (M & 3)) {
        uint32_t m = (uint32_t)((n4 << 2) + t);
        uint32_t b = g_scorebits[m];
        if (b >= T) {
            uint32_t p = atomicAdd(&g_cand_cnt, 1u);
            if (p < CAND_CAP)
                g_cand[p] = ((unsigned long long)b << 32) |
                            (unsigned long long)(0xFFFFFFFFu - m);
        }
    }
}

// ============================================================================
// K4: warp-per-candidate rank (ballot count) + warp-parallel argmax + fetch
//     128 blocks x 1024 threads (32 warps = 32 candidates per block)
// ============================================================================
__global__ void __launch_bounds__(1024) k_rank(const float* __restrict__ cls,
                                               const float4* __restrict__ boxp) {
    __shared__ unsigned long long keys[CAND_CAP];
    int t = threadIdx.x;
    uint32_t n = g_cand_cnt;
    if (n > CAND_CAP) n = CAND_CAP;
    if ((uint32_t)(blockIdx.x * 32) >= n) return;   // block-uniform early exit

    for (uint32_t i = t; i < n; i += 1024) keys[i] = g_cand[i];
    __syncthreads();

    int warp = t >> 5, lane = t & 31;
    uint32_t c = blockIdx.x * 32 + warp;
    if (c >= n) return;                              // warp-uniform
    unsigned long long k = keys[c];

    // warp-cooperative rank: lanes split the scan; count via ballot+popc
    int r = 0;
    for (uint32_t j0 = 0; j0 < n; j0 += 32) {
        uint32_t j = j0 + lane;
        bool p = (j < n) && (keys[j] > k);
        r += __popc(__ballot_sync(0xFFFFFFFFu, p));
    }
    if (r >= TOPK) return;

    uint32_t idx = 0xFFFFFFFFu - (uint32_t)(k & 0xFFFFFFFFull);

    // warp-parallel first-max argmax over 80 classes (20 lanes x 1 float4)
    float best = -1e30f;
    int lab = 0x7FFFFFFF;
    if (lane < 20) {
        float4 v = __ldg(&((const float4*)(cls + (size_t)idx * NCLS))[lane]);
        best = v.x; lab = lane * 4;
        if (v.y > best) { best = v.y; lab = lane * 4 + 1; }
        if (v.z > best) { best = v.z; lab = lane * 4 + 2; }
        if (v.w > best) { best = v.w; lab = lane * 4 + 3; }
    }
#pragma unroll
    for (int off = 16; off > 0; off >>= 1) {
        float ob = __shfl_down_sync(0xFFFFFFFFu, best, off);
        int   ol = __shfl_down_sync(0xFFFFFFFFu, lab, off);
        if (ob > best || (ob == best && ol < lab)) { best = ob; lab = ol; }
    }
    lab = __shfl_sync(0xFFFFFFFFu, lab, 0);          // first-max index

    if (lane == 0) {
        float scr = __uint_as_float((uint32_t)(k >> 32));
        float4 b = __ldg(&boxp[idx]);
        float off = (float)lab * CLSOFF;
        float x1 = b.x + off, y1 = b.y + off;
        float x2 = b.z + off, y2 = b.w + off;
        g_box[r] = b;
        g_scr[r] = scr;
        g_lab[r] = lab;
        g_x1[r] = x1; g_y1[r] = y1; g_x2[r] = x2; g_y2[r] = y2;
        g_area[r] = fmaxf(x2 - x1, 0.0f) * fmaxf(y2 - y1, 0.0f);
        if (scr > CONF) atomicOr(&g_keep0[r >> 5], 1u << (r & 31));
    }
}

// ============================================================================
// K5: suppression bit-matrix, grid-wide (32 blocks x 1024), boxes in smem
// ============================================================================
__global__ void k_sup() {
    __shared__ float sx1[TOPK], sy1[TOPK], sx2[TOPK], sy2[TOPK], sarea[TOPK];
    __shared__ int   slab[TOPK];
    int t = threadIdx.x;
    for (int i = t; i < TOPK; i += 1024) {
        sx1[i] = g_x1[i]; sy1[i] = g_y1[i];
        sx2[i] = g_x2[i]; sy2[i] = g_y2[i];
        sarea[i] = g_area[i]; slab[i] = g_lab[i];
    }
    __syncthreads();

    int w = t >> 5;          // j-word
    int lane = t & 31;       // row within this block's 32-row band
    int i = blockIdx.x * 32 + lane;
    int jbase = w * 32;
    uint32_t bits = 0;
    if (i < TOPK && jbase < i) {
        int lb = slab[i];
        float ix1 = sx1[i], iy1 = sy1[i], ix2 = sx2[i], iy2 = sy2[i];
        float ia = sarea[i];
        int jend = jbase + 32; if (jend > i) jend = i;
        for (int j = jbase; j < jend; j++) {
            if (slab[j] == lb) {   // cross-class IoU is exactly 0 (offset geometry)
                float xx1 = fmaxf(ix1, sx1[j]);
                float yy1 = fmaxf(iy1, sy1[j]);
                float xx2 = fminf(ix2, sx2[j]);
                float yy2 = fminf(iy2, sy2[j]);
                float inter = fmaxf(xx2 - xx1, 0.0f) * fmaxf(yy2 - yy1, 0.0f);
                float iou = inter / (ia + sarea[j] - inter + 1e-9f);
                if (iou > NMSTH) bits |= (1u << (j - jbase));
            }
        }
    }
    if (i < TOPK) {
        g_sup[i * 32 + w] = bits;
        if (bits) atomicOr(&g_rowNZ[i >> 5], 1u << (i & 31));
    }
}

// ============================================================================
// K6: sparse greedy sweep + output + state reset for next replay
// ============================================================================
__global__ void k_nms(float* __restrict__ out, int out_size) {
    __shared__ uint32_t srow[NLCAP * 32];   // 48 KB: staged contested rows
    __shared__ int      list[1024];
    __shared__ int      nlist;
    __shared__ uint32_t keep[32];
    __shared__ uint32_t rnz[32];

    int t = threadIdx.x;
    int lane = t & 31;
    if (t < 32) { keep[t] = g_keep0[t]; rnz[t] = g_rowNZ[t]; }
    __syncthreads();

    // warp 0: build ascending list of contested rows
    if (t < 32) {
        int cnt = 0;
        for (int w2 = 0; w2 < 32; w2++) {
            uint32_t rb = rnz[w2];
            int bit = (rb >> lane) & 1;
            uint32_t bal = __ballot_sync(0xFFFFFFFFu, bit);
            if (bit) {
                int pos = cnt + __popc(bal & ((1u << lane) - 1u));
                list[pos] = w2 * 32 + lane;
            }
            cnt += __popc(bal);
        }
        if (lane == 0) nlist = cnt;
    }
    __syncthreads();

    // stage contested rows (first NLCAP) into smem
    int nl = nlist;
    for (int l = t >> 5; l < nl && l < NLCAP; l += 32)
        srow[l * 32 + lane] = g_sup[list[l] * 32 + lane];
    __syncthreads();

    // warp 0: serial greedy sweep, lane owns keep-word lane
    if (t < 32) {
        uint32_t kw = keep[lane];
        for (int l = 0; l < nl; l++) {
            int i = list[l];
            int iw = i >> 5;
            uint32_t ib = (uint32_t)(i & 31);
            uint32_t ltm = (lane < iw) ? 0xFFFFFFFFu
                         : ((lane == iw) ? ((1u << ib) - 1u) : 0u);
            uint32_t row = (l < NLCAP) ? srow[l * 32 + lane]
                                       : g_sup[i * 32 + lane];
            uint32_t v = row & kw & ltm;
            if (__any_sync(0xFFFFFFFFu, v != 0u)) {
                if (lane == iw) kw &= ~(1u << ib);
            }
        }
        keep[lane] = kw;
    }
    __syncthreads();

    if (t < TOPK) {
        float kf = ((keep[t >> 5] >> (t & 31)) & 1u) ? 1.0f : 0.0f;
        float4 b = g_box[t];   // raw (un-offset) box, matches reference
        out[t * 5 + 0] = g_scr[t] * kf;
        out[t * 5 + 1] = b.x * kf;
        out[t * 5 + 2] = b.y * kf;
        out[t * 5 + 3] = b.z * kf;
        out[t * 5 + 4] = b.w * kf;
        if (out_size >= 6000) out[5000 + t] = (float)g_lab[t];
        if (out_size >= 7000) out[6000 + t] = kf;
    }

    // ---- reset all scratch state for the next replay ----
    for (int i = t; i < NBINS; i += 1024) { g_hist1[i] = 0; g_hist2[i] = 0; }
    if (t < 32) { g_rowNZ[t] = 0; g_keep0[t] = 0; }
    if (t == 0) g_cand_cnt = 0;
}

// ---------------- launch (6 kernels) ----------------
extern "C" void kernel_launch(void* const* d_in, const int* in_sizes, int n_in,
                              void* d_out, int out_size) {
    const float* obj   = (const float*)d_in[0];
    const float* cls   = (const float*)d_in[1];
    const float4* boxp = (const float4*)d_in[2];
    float* out = (float*)d_out;
    int M = in_sizes[0];
    if (M > MAXM) M = MAXM;
    (void)n_in;

    int gsc = (M + 511) / 512;
    int n4 = M >> 2;
    int gb = (n4 + 1023) / 1024;
    if (gb > 148) gb = 148;
    if (gb < 1) gb = 1;

    k_score<<<gsc, 512>>>(obj, cls, M);
    k_hist2<<<gb, 1024>>>(M);
    k_gather<<<gb, 1024>>>(M);
    k_rank<<<CAND_CAP / 32, 1024>>>(cls, boxp);
    k_sup<<<(TOPK + 31) / 32, 1024>>>();
    k_nms<<<1, 1024>>>(out, out_size);
}